// round 1
// baseline (speedup 1.0000x reference)
#include <cuda_runtime.h>
#include <cuda_bf16.h>

#define NN   50000
#define NE   800000
#define HIDD 128
#define EIND 273
#define TE   64
#define NT   256

// Scratch (device globals: no allocation allowed)
__device__ float g_agg[(size_t)NN * HIDD];
__device__ float g_cs[NN * 3];
__device__ float g_cnt[NN];

__device__ __forceinline__ float silu_f(float x) {
    return x / (1.0f + __expf(-x));
}

// ---------------- Edge kernel ----------------
// smem layout (floats):
//   s_ein [273][64]   @ 0       (17472)
//   s_w   [16][128]   @ 17472   (2048)
//   s_m1  [64][132]   @ 19520   (8448)
//   s_m   [64][132]   @ 27968   (8448)
//   s_row [64] (int)  @ 36416
//   s_col [64] (int)  @ 36480
//   s_d   [3][64]     @ 36544
//   s_wgt [64]        @ 36736
// total 36800 floats = 147200 bytes
#define EDGE_SMEM_FLOATS 36800
#define EDGE_SMEM_BYTES  (EDGE_SMEM_FLOATS * 4)

extern __shared__ float smem_f[];

__global__ void __launch_bounds__(NT, 1) edge_kernel(
    const float* __restrict__ h, const float* __restrict__ coord,
    const float* __restrict__ eattr, const int* __restrict__ ei,
    const float* __restrict__ We1, const float* __restrict__ be1,
    const float* __restrict__ We2, const float* __restrict__ be2,
    const float* __restrict__ Wc1, const float* __restrict__ bc1,
    const float* __restrict__ Wc2, const float* __restrict__ bc2,
    float* __restrict__ m_out, float* __restrict__ agg,
    float* __restrict__ cs, float* __restrict__ cnt)
{
    float* s_ein = smem_f;
    float* s_w   = smem_f + 17472;
    float* s_m1  = smem_f + 19520;
    float* s_m   = smem_f + 27968;
    int*   s_row = (int*)(smem_f + 36416);
    int*   s_col = (int*)(smem_f + 36480);
    float* s_d   = smem_f + 36544;
    float* s_wgt = smem_f + 36736;

    const int tid   = threadIdx.x;
    const int eb    = blockIdx.x * TE;
    const int lane  = tid & 31;
    const int warp  = tid >> 5;
    const int ebase = warp * 8;

    // Phase 0: indices, displacement, radial
    if (tid < TE) {
        int g = eb + tid;
        int r = ei[g], c = ei[NE + g];
        s_row[tid] = r; s_col[tid] = c;
        float dx = coord[r*3+0] - coord[c*3+0];
        float dy = coord[r*3+1] - coord[c*3+1];
        float dz = coord[r*3+2] - coord[c*3+2];
        s_d[0*64+tid] = dx; s_d[1*64+tid] = dy; s_d[2*64+tid] = dz;
        s_ein[256*64 + tid] = dx*dx + dy*dy + dz*dz;
    }
    __syncthreads();

    // Phase 1: build e_in columns (k-major)
    {
        int e = tid >> 2, q = tid & 3;  // 4 threads per edge
        const float* hr = h + (size_t)s_row[e] * HIDD + q * 32;
        const float* hc = h + (size_t)s_col[e] * HIDD + q * 32;
        #pragma unroll
        for (int i = 0; i < 8; i++) {
            float4 v = *(const float4*)(hr + i*4);
            int k = q*32 + i*4;
            s_ein[(k+0)*64+e] = v.x; s_ein[(k+1)*64+e] = v.y;
            s_ein[(k+2)*64+e] = v.z; s_ein[(k+3)*64+e] = v.w;
        }
        #pragma unroll
        for (int i = 0; i < 8; i++) {
            float4 v = *(const float4*)(hc + i*4);
            int k = 128 + q*32 + i*4;
            s_ein[(k+0)*64+e] = v.x; s_ein[(k+1)*64+e] = v.y;
            s_ein[(k+2)*64+e] = v.z; s_ein[(k+3)*64+e] = v.w;
        }
    }
    for (int idx = tid; idx < TE * 16; idx += NT) {
        int e = idx >> 4, j = idx & 15;
        s_ein[(257+j)*64 + e] = eattr[(size_t)(eb+e)*16 + j];
    }
    __syncthreads();

    float acc[8][4];
    #pragma unroll
    for (int i = 0; i < 8; i++)
        #pragma unroll
        for (int j = 0; j < 4; j++) acc[i][j] = 0.0f;

    // GEMM1: [64 x 273] @ [273 x 128]
    for (int kb = 0; kb < EIND; kb += 16) {
        int kc = min(16, EIND - kb);
        for (int idx = tid; idx < kc * 128; idx += NT)
            s_w[idx] = We1[kb*128 + idx];
        __syncthreads();
        if (kc == 16) {
            #pragma unroll
            for (int k = 0; k < 16; k++) {
                float4 a0 = *(const float4*)&s_ein[(kb+k)*64 + ebase];
                float4 a1 = *(const float4*)&s_ein[(kb+k)*64 + ebase + 4];
                float4 b  = *(const float4*)&s_w[k*128 + lane*4];
                float av[8] = {a0.x,a0.y,a0.z,a0.w,a1.x,a1.y,a1.z,a1.w};
                float bv[4] = {b.x,b.y,b.z,b.w};
                #pragma unroll
                for (int i = 0; i < 8; i++)
                    #pragma unroll
                    for (int j = 0; j < 4; j++)
                        acc[i][j] = fmaf(av[i], bv[j], acc[i][j]);
            }
        } else {
            for (int k = 0; k < kc; k++) {
                float4 a0 = *(const float4*)&s_ein[(kb+k)*64 + ebase];
                float4 a1 = *(const float4*)&s_ein[(kb+k)*64 + ebase + 4];
                float4 b  = *(const float4*)&s_w[k*128 + lane*4];
                float av[8] = {a0.x,a0.y,a0.z,a0.w,a1.x,a1.y,a1.z,a1.w};
                float bv[4] = {b.x,b.y,b.z,b.w};
                #pragma unroll
                for (int i = 0; i < 8; i++)
                    #pragma unroll
                    for (int j = 0; j < 4; j++)
                        acc[i][j] = fmaf(av[i], bv[j], acc[i][j]);
            }
        }
        __syncthreads();
    }

    // Epilogue 1: bias + silu -> s_m1 (edge-major, stride 132)
    {
        float4 b1 = *(const float4*)&be1[lane*4];
        float bv[4] = {b1.x,b1.y,b1.z,b1.w};
        #pragma unroll
        for (int i = 0; i < 8; i++) {
            float4 o;
            o.x = silu_f(acc[i][0] + bv[0]);
            o.y = silu_f(acc[i][1] + bv[1]);
            o.z = silu_f(acc[i][2] + bv[2]);
            o.w = silu_f(acc[i][3] + bv[3]);
            *(float4*)&s_m1[(ebase+i)*132 + lane*4] = o;
        }
    }
    #pragma unroll
    for (int i = 0; i < 8; i++)
        #pragma unroll
        for (int j = 0; j < 4; j++) acc[i][j] = 0.0f;

    // GEMM2: m1 @ We2 (K=128)
    for (int kb = 0; kb < 128; kb += 16) {
        for (int idx = tid; idx < 16 * 128; idx += NT)
            s_w[idx] = We2[kb*128 + idx];
        __syncthreads();
        #pragma unroll
        for (int k = 0; k < 16; k++) {
            float4 b = *(const float4*)&s_w[k*128 + lane*4];
            float bv[4] = {b.x,b.y,b.z,b.w};
            float av[8];
            #pragma unroll
            for (int i = 0; i < 8; i++)
                av[i] = s_m1[(ebase+i)*132 + kb + k];
            #pragma unroll
            for (int i = 0; i < 8; i++)
                #pragma unroll
                for (int j = 0; j < 4; j++)
                    acc[i][j] = fmaf(av[i], bv[j], acc[i][j]);
        }
        __syncthreads();
    }

    // Epilogue 2: bias + silu -> s_m
    {
        float4 b2 = *(const float4*)&be2[lane*4];
        float bv[4] = {b2.x,b2.y,b2.z,b2.w};
        #pragma unroll
        for (int i = 0; i < 8; i++) {
            float4 o;
            o.x = silu_f(acc[i][0] + bv[0]);
            o.y = silu_f(acc[i][1] + bv[1]);
            o.z = silu_f(acc[i][2] + bv[2]);
            o.w = silu_f(acc[i][3] + bv[3]);
            *(float4*)&s_m[(ebase+i)*132 + lane*4] = o;
        }
    }
    #pragma unroll
    for (int i = 0; i < 8; i++)
        #pragma unroll
        for (int j = 0; j < 4; j++) acc[i][j] = 0.0f;

    // GEMM3: m @ Wc1 (K=128), then silu * Wc2 reduce -> per-edge scalar w
    for (int kb = 0; kb < 128; kb += 16) {
        for (int idx = tid; idx < 16 * 128; idx += NT)
            s_w[idx] = Wc1[kb*128 + idx];
        __syncthreads();
        #pragma unroll
        for (int k = 0; k < 16; k++) {
            float4 b = *(const float4*)&s_w[k*128 + lane*4];
            float bv[4] = {b.x,b.y,b.z,b.w};
            float av[8];
            #pragma unroll
            for (int i = 0; i < 8; i++)
                av[i] = s_m[(ebase+i)*132 + kb + k];
            #pragma unroll
            for (int i = 0; i < 8; i++)
                #pragma unroll
                for (int j = 0; j < 4; j++)
                    acc[i][j] = fmaf(av[i], bv[j], acc[i][j]);
        }
        __syncthreads();
    }
    {
        float4 bc = *(const float4*)&bc1[lane*4];
        float4 wc = *(const float4*)&Wc2[lane*4];
        float bc2v = bc2[0];
        float ws[8];
        #pragma unroll
        for (int i = 0; i < 8; i++) {
            float s = silu_f(acc[i][0] + bc.x) * wc.x;
            s = fmaf(silu_f(acc[i][1] + bc.y), wc.y, s);
            s = fmaf(silu_f(acc[i][2] + bc.z), wc.z, s);
            s = fmaf(silu_f(acc[i][3] + bc.w), wc.w, s);
            ws[i] = s;
        }
        #pragma unroll
        for (int off = 16; off >= 1; off >>= 1)
            #pragma unroll
            for (int i = 0; i < 8; i++)
                ws[i] += __shfl_xor_sync(0xFFFFFFFFu, ws[i], off);
        if (lane == 0) {
            #pragma unroll
            for (int i = 0; i < 8; i++)
                s_wgt[ebase + i] = ws[i] + bc2v;
        }
    }
    __syncthreads();

    // Scatter: m to global + agg atomics
    for (int idx = tid; idx < TE * HIDD; idx += NT) {
        int e = idx >> 7, k = idx & 127;
        float v = s_m[e*132 + k];
        m_out[(size_t)(eb+e)*HIDD + k] = v;
        atomicAdd(&agg[(size_t)s_row[e]*HIDD + k], v);
    }
    if (tid < TE) {
        float w = s_wgt[tid];
        int r = s_row[tid];
        atomicAdd(&cs[r*3+0], s_d[0*64+tid] * w);
        atomicAdd(&cs[r*3+1], s_d[1*64+tid] * w);
        atomicAdd(&cs[r*3+2], s_d[2*64+tid] * w);
        atomicAdd(&cnt[r], 1.0f);
    }
}

// ---------------- Node kernel ----------------
// smem floats: s_nin [64][260] @0 (16640), s_w [16][128] @16640 (2048),
//              s_h1 [64][132] @18688 (8448) -> total 27136 floats = 108544 B
#define NODE_SMEM_FLOATS 27136
#define NODE_SMEM_BYTES  (NODE_SMEM_FLOATS * 4)

__global__ void __launch_bounds__(NT, 1) node_kernel(
    const float* __restrict__ h, const float* __restrict__ coord,
    const float* __restrict__ Wn1, const float* __restrict__ bn1,
    const float* __restrict__ Wn2, const float* __restrict__ bn2,
    const float* __restrict__ agg, const float* __restrict__ cs,
    const float* __restrict__ cnt,
    float* __restrict__ h_out, float* __restrict__ c_out)
{
    float* s_nin = smem_f;
    float* s_w   = smem_f + 16640;
    float* s_h1  = smem_f + 18688;

    const int tid   = threadIdx.x;
    const int nb    = blockIdx.x * 64;
    const int lane  = tid & 31;
    const int warp  = tid >> 5;
    const int ebase = warp * 8;

    // Build n_in = [h | agg] (node-major, stride 260)
    for (int idx = tid; idx < 64 * 64; idx += NT) {
        int n = idx >> 6, f = idx & 63;
        int node = nb + n;
        float4 v = make_float4(0.f, 0.f, 0.f, 0.f);
        if (node < NN) {
            if (f < 32) v = *(const float4*)(h + (size_t)node*HIDD + f*4);
            else        v = *(const float4*)(agg + (size_t)node*HIDD + (f-32)*4);
        }
        *(float4*)&s_nin[n*260 + f*4] = v;
    }
    __syncthreads();

    float acc[8][4];
    #pragma unroll
    for (int i = 0; i < 8; i++)
        #pragma unroll
        for (int j = 0; j < 4; j++) acc[i][j] = 0.0f;

    // GEMM A: n_in @ Wn1 (K=256)
    for (int kb = 0; kb < 256; kb += 16) {
        for (int idx = tid; idx < 16 * 128; idx += NT)
            s_w[idx] = Wn1[kb*128 + idx];
        __syncthreads();
        #pragma unroll
        for (int k = 0; k < 16; k++) {
            float4 b = *(const float4*)&s_w[k*128 + lane*4];
            float bv[4] = {b.x,b.y,b.z,b.w};
            float av[8];
            #pragma unroll
            for (int i = 0; i < 8; i++)
                av[i] = s_nin[(ebase+i)*260 + kb + k];
            #pragma unroll
            for (int i = 0; i < 8; i++)
                #pragma unroll
                for (int j = 0; j < 4; j++)
                    acc[i][j] = fmaf(av[i], bv[j], acc[i][j]);
        }
        __syncthreads();
    }
    {
        float4 b1 = *(const float4*)&bn1[lane*4];
        float bv[4] = {b1.x,b1.y,b1.z,b1.w};
        #pragma unroll
        for (int i = 0; i < 8; i++) {
            float4 o;
            o.x = silu_f(acc[i][0] + bv[0]);
            o.y = silu_f(acc[i][1] + bv[1]);
            o.z = silu_f(acc[i][2] + bv[2]);
            o.w = silu_f(acc[i][3] + bv[3]);
            *(float4*)&s_h1[(ebase+i)*132 + lane*4] = o;
        }
    }
    #pragma unroll
    for (int i = 0; i < 8; i++)
        #pragma unroll
        for (int j = 0; j < 4; j++) acc[i][j] = 0.0f;

    // GEMM B: h1 @ Wn2 (K=128)
    for (int kb = 0; kb < 128; kb += 16) {
        for (int idx = tid; idx < 16 * 128; idx += NT)
            s_w[idx] = Wn2[kb*128 + idx];
        __syncthreads();
        #pragma unroll
        for (int k = 0; k < 16; k++) {
            float4 b = *(const float4*)&s_w[k*128 + lane*4];
            float bv[4] = {b.x,b.y,b.z,b.w};
            float av[8];
            #pragma unroll
            for (int i = 0; i < 8; i++)
                av[i] = s_h1[(ebase+i)*132 + kb + k];
            #pragma unroll
            for (int i = 0; i < 8; i++)
                #pragma unroll
                for (int j = 0; j < 4; j++)
                    acc[i][j] = fmaf(av[i], bv[j], acc[i][j]);
        }
        __syncthreads();
    }
    {
        float4 b2 = *(const float4*)&bn2[lane*4];
        #pragma unroll
        for (int i = 0; i < 8; i++) {
            int node = nb + ebase + i;
            if (node < NN) {
                float4 o;
                o.x = acc[i][0] + b2.x;
                o.y = acc[i][1] + b2.y;
                o.z = acc[i][2] + b2.z;
                o.w = acc[i][3] + b2.w;
                *(float4*)&h_out[(size_t)node*HIDD + lane*4] = o;
            }
        }
    }

    // coord update
    if (tid < 64) {
        int node = nb + tid;
        if (node < NN) {
            float c = cnt[node];
            float dn = fmaxf(c, 1.0f);
            #pragma unroll
            for (int d = 0; d < 3; d++)
                c_out[node*3 + d] = coord[node*3 + d] + cs[node*3 + d] / dn;
        }
    }
}

extern "C" void kernel_launch(void* const* d_in, const int* in_sizes, int n_in,
                              void* d_out, int out_size)
{
    const float* h     = (const float*)d_in[0];
    const float* coord = (const float*)d_in[1];
    const float* eattr = (const float*)d_in[2];
    const int*   ei    = (const int*)d_in[3];
    const float* We1   = (const float*)d_in[4];
    const float* be1   = (const float*)d_in[5];
    const float* We2   = (const float*)d_in[6];
    const float* be2   = (const float*)d_in[7];
    const float* Wn1   = (const float*)d_in[8];
    const float* bn1   = (const float*)d_in[9];
    const float* Wn2   = (const float*)d_in[10];
    const float* bn2   = (const float*)d_in[11];
    const float* Wc1   = (const float*)d_in[12];
    const float* bc1   = (const float*)d_in[13];
    const float* Wc2   = (const float*)d_in[14];
    const float* bc2   = (const float*)d_in[15];

    float* out   = (float*)d_out;
    float* h_out = out;                                 // [NN,128]
    float* c_out = out + (size_t)NN * HIDD;             // [NN,3]
    float* m_out = c_out + (size_t)NN * 3;              // [NE,128]

    void *p_agg, *p_cs, *p_cnt;
    cudaGetSymbolAddress(&p_agg, g_agg);
    cudaGetSymbolAddress(&p_cs, g_cs);
    cudaGetSymbolAddress(&p_cnt, g_cnt);
    cudaMemsetAsync(p_agg, 0, (size_t)NN * HIDD * sizeof(float), 0);
    cudaMemsetAsync(p_cs, 0, (size_t)NN * 3 * sizeof(float), 0);
    cudaMemsetAsync(p_cnt, 0, (size_t)NN * sizeof(float), 0);

    cudaFuncSetAttribute(edge_kernel, cudaFuncAttributeMaxDynamicSharedMemorySize, EDGE_SMEM_BYTES);
    cudaFuncSetAttribute(node_kernel, cudaFuncAttributeMaxDynamicSharedMemorySize, NODE_SMEM_BYTES);

    edge_kernel<<<NE / TE, NT, EDGE_SMEM_BYTES>>>(
        h, coord, eattr, ei, We1, be1, We2, be2, Wc1, bc1, Wc2, bc2,
        m_out, (float*)p_agg, (float*)p_cs, (float*)p_cnt);

    node_kernel<<<(NN + 63) / 64, NT, NODE_SMEM_BYTES>>>(
        h, coord, Wn1, bn1, Wn2, bn2,
        (const float*)p_agg, (const float*)p_cs, (const float*)p_cnt,
        h_out, c_out);
}